// round 2
// baseline (speedup 1.0000x reference)
#include <cuda_runtime.h>
#include <cuda_bf16.h>
#include <cstdint>

// Problem constants (fixed by the reference)
#define BATCH  2
#define SEQ    2048
#define DMODEL 1024
#define NH     16
#define DHEAD  64
#define MROWS  (BATCH * SEQ)        // 4096

// Scratch (device globals; no allocation allowed in kernel_launch)
__device__ float g_q[BATCH * NH * SEQ * DHEAD];     // [B,H,N,DH]
__device__ float g_k[BATCH * NH * SEQ * DHEAD];
__device__ float g_v[BATCH * NH * SEQ * DHEAD];
__device__ float g_attn[BATCH * SEQ * DMODEL];      // [B,N,D] pre out-proj

// ---------------------------------------------------------------------------
// SGEMM: C[M,Ncols] = A[M,K] * B[K,Ncols] + bias[Ncols]
// 128x128 tile, BK=16, 256 threads, 8x8 per-thread register tile.
// MODE 0: A = g_attn (device global), write C directly.
// MODE 1: A = Ain param, epilogue scatters into g_q/g_k/g_v ([B,H,N,DH]).
// ---------------------------------------------------------------------------
template <int MODE>
__global__ __launch_bounds__(256, 2)
void sgemm_kernel(const float* __restrict__ Ain,
                  const float* __restrict__ Bm,
                  const float* __restrict__ bias,
                  float* __restrict__ C,
                  int M, int Ncols, int Kdim)
{
    const float* A = (MODE == 0) ? (const float*)g_attn : Ain;

    __shared__ float As[16][132];   // transposed A tile, padded
    __shared__ float Bs[16][128];

    const int tid = threadIdx.x;
    const int tx = tid & 15;        // 0..15 -> output cols (tx*8)
    const int ty = tid >> 4;        // 0..15 -> output rows (ty*8)
    const int bm = blockIdx.y * 128;
    const int bn = blockIdx.x * 128;

    float acc[8][8];
#pragma unroll
    for (int i = 0; i < 8; ++i)
#pragma unroll
        for (int j = 0; j < 8; ++j) acc[i][j] = 0.f;

    const int arow = tid >> 2;           // 0..63
    const int acol = (tid & 3) * 4;      // 0,4,8,12
    const int brow = tid >> 5;           // 0..7
    const int bcol = (tid & 31) * 4;     // 0..124

    for (int k0 = 0; k0 < Kdim; k0 += 16) {
        // Load A tile (128x16), store transposed
#pragma unroll
        for (int p = 0; p < 2; ++p) {
            int r = arow + p * 64;
            float4 av = *(const float4*)(A + (size_t)(bm + r) * Kdim + k0 + acol);
            As[acol + 0][r] = av.x;
            As[acol + 1][r] = av.y;
            As[acol + 2][r] = av.z;
            As[acol + 3][r] = av.w;
        }
        // Load B tile (16x128)
#pragma unroll
        for (int p = 0; p < 2; ++p) {
            int r = brow + p * 8;
            *(float4*)(&Bs[r][bcol]) =
                *(const float4*)(Bm + (size_t)(k0 + r) * Ncols + bn + bcol);
        }
        __syncthreads();

#pragma unroll
        for (int kk = 0; kk < 16; ++kk) {
            float a[8], b[8];
            *(float4*)(a)     = *(const float4*)(&As[kk][ty * 8]);
            *(float4*)(a + 4) = *(const float4*)(&As[kk][ty * 8 + 4]);
            *(float4*)(b)     = *(const float4*)(&Bs[kk][tx * 8]);
            *(float4*)(b + 4) = *(const float4*)(&Bs[kk][tx * 8 + 4]);
#pragma unroll
            for (int i = 0; i < 8; ++i)
#pragma unroll
                for (int j = 0; j < 8; ++j)
                    acc[i][j] = fmaf(a[i], b[j], acc[i][j]);
        }
        __syncthreads();
    }

    // Epilogue
#pragma unroll
    for (int i = 0; i < 8; ++i) {
        int m = bm + ty * 8 + i;
#pragma unroll
        for (int j = 0; j < 8; ++j) {
            int n = bn + tx * 8 + j;
            float v = acc[i][j] + bias[n];
            if (MODE == 0) {
                C[(size_t)m * Ncols + n] = v;
            } else {
                // n in [0, 3*DMODEL): [which][h][dh]
                int which = n >> 10;           // 0=q 1=k 2=v
                int d     = n & 1023;
                int h     = d >> 6;
                int dh    = d & 63;
                int bb    = m >> 11;           // m / SEQ
                int nn    = m & 2047;          // m % SEQ
                size_t idx = (((size_t)(bb * NH + h)) * SEQ + nn) * DHEAD + dh;
                if (which == 0)      g_q[idx] = v;
                else if (which == 1) g_k[idx] = v;
                else                 g_v[idx] = v;
            }
        }
    }
}

// ---------------------------------------------------------------------------
// Flash attention, fp32. One block = one (b,h) and a 128-query tile.
// 256 threads, per-thread 8 rows x 4 cols. Online softmax in base-2 domain.
// Smem: Qs[128][64] rowmajor, Ks[64][64] transposed+swizzled, Vs[64][64],
//       Ps[128][64] rowmajor. Total 96 KB (dynamic).
// ---------------------------------------------------------------------------
#define BQ  128
#define BKV 64
#define ATTN_SMEM ((BQ*64 + 64*64 + 64*64 + BQ*64) * 4)
static_assert(ATTN_SMEM == 96 * 1024, "attention smem budget changed");

__global__ __launch_bounds__(256, 2)
void attn_kernel()
{
    extern __shared__ float sm[];
    float* Qs = sm;                  // [BQ][64]
    float* Ks = Qs + BQ * 64;        // [64 d][64 j] swizzled on j-chunks
    float* Vs = Ks + 64 * 64;        // [64 j][64 dh]
    float* Ps = Vs + 64 * 64;        // [BQ][64 j]

    const int tid  = threadIdx.x;
    const int tcol = tid & 15;       // 0..15
    const int trow = tid >> 4;       // 0..15
    const int bh    = blockIdx.y;    // 0..31  (b = bh>>4, h = bh&15)
    const int qtile = blockIdx.x;    // 0..15

    const float* Q = g_q + (size_t)bh * SEQ * DHEAD + (size_t)qtile * BQ * DHEAD;
    const float* K = g_k + (size_t)bh * SEQ * DHEAD;
    const float* V = g_v + (size_t)bh * SEQ * DHEAD;

    // Load Q tile (128x64) row-major
    {
        int d0 = tcol * 4;
#pragma unroll
        for (int it = 0; it < 8; ++it) {
            int i = trow + it * 16;
            *(float4*)(Qs + i * 64 + d0) = *(const float4*)(Q + (size_t)i * DHEAD + d0);
        }
    }

    float o[8][4];
    float m2[8], lsum[8];
#pragma unroll
    for (int r = 0; r < 8; ++r) {
        m2[r] = -1e30f; lsum[r] = 0.f;
#pragma unroll
        for (int c = 0; c < 4; ++c) o[r][c] = 0.f;
    }

    const float scale2 = 0.125f * 1.4426950408889634f;  // 1/sqrt(DH) * log2(e)
    const int i0 = trow * 8;
    const int j0 = tcol * 4;

    for (int kt = 0; kt < SEQ / BKV; ++kt) {
        __syncthreads();   // prev-iter reads of Ks/Vs/Ps done; kt=0: Qs visible
        // Load K tile transposed+swizzled and V tile row-major
        {
            int d0 = tcol * 4;
#pragma unroll
            for (int it = 0; it < 4; ++it) {
                int j = trow + it * 16;
                float4 kv = *(const float4*)(K + (size_t)(kt * BKV + j) * DHEAD + d0);
                const float* kp = (const float*)&kv;
#pragma unroll
                for (int c = 0; c < 4; ++c) {
                    int d = d0 + c;
                    int chunk = (j >> 2) ^ ((d >> 2) & 15);
                    Ks[d * 64 + chunk * 4 + (j & 3)] = kp[c];
                }
                *(float4*)(Vs + j * 64 + d0) =
                    *(const float4*)(V + (size_t)(kt * BKV + j) * DHEAD + d0);
            }
        }
        __syncthreads();

        // S = Q @ K^T  (8x4 per thread)
        float s[8][4];
#pragma unroll
        for (int r = 0; r < 8; ++r)
#pragma unroll
            for (int c = 0; c < 4; ++c) s[r][c] = 0.f;

#pragma unroll 4
        for (int d = 0; d < 64; d += 4) {
            float bl[4][4];
#pragma unroll
            for (int dd = 0; dd < 4; ++dd) {
                int ddd = d + dd;
                int chunk = tcol ^ ((ddd >> 2) & 15);
                *(float4*)bl[dd] = *(const float4*)(Ks + ddd * 64 + chunk * 4);
            }
#pragma unroll
            for (int r = 0; r < 8; ++r) {
                float4 a4 = *(const float4*)(Qs + (i0 + r) * 64 + d);
#pragma unroll
                for (int c = 0; c < 4; ++c) {
                    s[r][c] = fmaf(a4.x, bl[0][c], s[r][c]);
                    s[r][c] = fmaf(a4.y, bl[1][c], s[r][c]);
                    s[r][c] = fmaf(a4.z, bl[2][c], s[r][c]);
                    s[r][c] = fmaf(a4.w, bl[3][c], s[r][c]);
                }
            }
        }

        // Online softmax (base-2), reductions over 16-lane row groups
#pragma unroll
        for (int r = 0; r < 8; ++r) {
            float rmax = -1e30f;
#pragma unroll
            for (int c = 0; c < 4; ++c) {
                s[r][c] *= scale2;
                rmax = fmaxf(rmax, s[r][c]);
            }
#pragma unroll
            for (int off = 8; off >= 1; off >>= 1)
                rmax = fmaxf(rmax, __shfl_xor_sync(0xffffffffu, rmax, off));

            float mnew  = fmaxf(m2[r], rmax);
            float alpha = exp2f(m2[r] - mnew);
            float rs = 0.f;
#pragma unroll
            for (int c = 0; c < 4; ++c) {
                float p = exp2f(s[r][c] - mnew);
                s[r][c] = p;
                rs += p;
            }
#pragma unroll
            for (int off = 8; off >= 1; off >>= 1)
                rs += __shfl_xor_sync(0xffffffffu, rs, off);

            lsum[r] = lsum[r] * alpha + rs;
            m2[r]   = mnew;
#pragma unroll
            for (int c = 0; c < 4; ++c) o[r][c] *= alpha;

            *(float4*)(Ps + (i0 + r) * 64 + j0) =
                make_float4(s[r][0], s[r][1], s[r][2], s[r][3]);
        }
        __syncthreads();

        // O += P @ V   (dh columns = tcol*4 .. +3)
#pragma unroll 4
        for (int j = 0; j < 64; j += 4) {
            float bl[4][4];
#pragma unroll
            for (int jj = 0; jj < 4; ++jj)
                *(float4*)bl[jj] = *(const float4*)(Vs + (j + jj) * 64 + tcol * 4);
#pragma unroll
            for (int r = 0; r < 8; ++r) {
                float4 a4 = *(const float4*)(Ps + (i0 + r) * 64 + j);
#pragma unroll
                for (int c = 0; c < 4; ++c) {
                    o[r][c] = fmaf(a4.x, bl[0][c], o[r][c]);
                    o[r][c] = fmaf(a4.y, bl[1][c], o[r][c]);
                    o[r][c] = fmaf(a4.z, bl[2][c], o[r][c]);
                    o[r][c] = fmaf(a4.w, bl[3][c], o[r][c]);
                }
            }
        }
    }

    // Normalize + write to g_attn [B,N,D] with D index = h*64 + dh
    const int b = bh >> 4;
    const int h = bh & 15;
#pragma unroll
    for (int r = 0; r < 8; ++r) {
        float inv = __frcp_rn(lsum[r]);
        int n = qtile * BQ + i0 + r;
        float4 v4 = make_float4(o[r][0] * inv, o[r][1] * inv,
                                o[r][2] * inv, o[r][3] * inv);
        *(float4*)(g_attn + ((size_t)(b * SEQ + n)) * DMODEL + h * DHEAD + tcol * 4) = v4;
    }
}

// ---------------------------------------------------------------------------
extern "C" void kernel_launch(void* const* d_in, const int* in_sizes, int n_in,
                              void* d_out, int out_size)
{
    const float* x     = (const float*)d_in[0];   // [2,2048,1024]
    const float* Wqkv  = (const float*)d_in[1];   // [1024,3072]
    const float* bqkv  = (const float*)d_in[2];   // [3072]
    const float* Wout  = (const float*)d_in[3];   // [1024,1024]
    const float* bout  = (const float*)d_in[4];   // [1024]
    float* out = (float*)d_out;                   // [2,2048,1024]

    // Opt-in smem for the attention kernel (host-side attribute set; legal
    // during capture, idempotent, and exercised in the correctness pass first).
    cudaFuncSetAttribute(attn_kernel,
                         cudaFuncAttributeMaxDynamicSharedMemorySize,
                         ATTN_SMEM);

    // 1) QKV projection -> g_q/g_k/g_v
    {
        dim3 grid(3 * DMODEL / 128, MROWS / 128);   // 24 x 32
        sgemm_kernel<1><<<grid, 256>>>(x, Wqkv, bqkv, nullptr,
                                       MROWS, 3 * DMODEL, DMODEL);
    }

    // 2) Flash attention -> g_attn
    {
        dim3 grid(SEQ / BQ, BATCH * NH);            // 16 x 32
        attn_kernel<<<grid, 256, ATTN_SMEM>>>();
    }

    // 3) Output projection -> out
    {
        dim3 grid(DMODEL / 128, MROWS / 128);       // 8 x 32
        sgemm_kernel<0><<<grid, 256>>>(nullptr, Wout, bout, out,
                                       MROWS, DMODEL, DMODEL);
    }
}

// round 5
// speedup vs baseline: 1.3490x; 1.3490x over previous
#include <cuda_runtime.h>
#include <cuda_bf16.h>
#include <cstdint>

// Problem constants
#define BATCH  2
#define SEQ    2048
#define DMODEL 1024
#define NH     16
#define DHEAD  64
#define MROWS  4096
#define KDIM   1024

// ---------------------------------------------------------------------------
// Device-global scratch
// ---------------------------------------------------------------------------
__device__ float g_q[BATCH * NH * SEQ * DHEAD];     // [B,H,N,DH] fp32
__device__ float g_k[BATCH * NH * SEQ * DHEAD];
__device__ float g_v[BATCH * NH * SEQ * DHEAD];

__device__ __nv_bfloat16 g_xh[MROWS * KDIM];        // x split (row-major, K-major)
__device__ __nv_bfloat16 g_xl[MROWS * KDIM];
__device__ __nv_bfloat16 g_wqkvh[3 * DMODEL * KDIM];// W_qkv^T split: [3072][1024]
__device__ __nv_bfloat16 g_wqkvl[3 * DMODEL * KDIM];
__device__ __nv_bfloat16 g_wouth[DMODEL * KDIM];    // W_out^T split: [1024][1024]
__device__ __nv_bfloat16 g_woutl[DMODEL * KDIM];
__device__ __nv_bfloat16 g_aoh[MROWS * DMODEL];     // attention output split
__device__ __nv_bfloat16 g_aol[MROWS * DMODEL];

// ---------------------------------------------------------------------------
// PTX helpers: ldmatrix / mma.sync (bf16) / cp.async — all legal on compute_100
// ---------------------------------------------------------------------------
__device__ __forceinline__ uint32_t smem_to_u32(const void* p) {
    uint32_t a;
    asm("{ .reg .u64 t; cvta.to.shared.u64 t, %1; cvt.u32.u64 %0, t; }"
        : "=r"(a) : "l"(p));
    return a;
}
__device__ __forceinline__ void ldsm_x4(uint32_t* r, uint32_t addr) {
    asm volatile("ldmatrix.sync.aligned.m8n8.x4.shared.b16 {%0,%1,%2,%3}, [%4];"
                 : "=r"(r[0]), "=r"(r[1]), "=r"(r[2]), "=r"(r[3]) : "r"(addr));
}
__device__ __forceinline__ void mma16816(float* c, const uint32_t* a, const uint32_t* b) {
    asm volatile("mma.sync.aligned.m16n8k16.row.col.f32.bf16.bf16.f32 "
                 "{%0,%1,%2,%3}, {%4,%5,%6,%7}, {%8,%9}, {%0,%1,%2,%3};"
                 : "+f"(c[0]), "+f"(c[1]), "+f"(c[2]), "+f"(c[3])
                 : "r"(a[0]), "r"(a[1]), "r"(a[2]), "r"(a[3]), "r"(b[0]), "r"(b[1]));
}
__device__ __forceinline__ void cp16(uint32_t dst, const void* src) {
    asm volatile("cp.async.cg.shared.global [%0], [%1], 16;" :: "r"(dst), "l"(src));
}
#define CP_COMMIT() asm volatile("cp.async.commit_group;" ::: "memory")
#define CP_WAIT1()  asm volatile("cp.async.wait_group 1;" ::: "memory")
#define CP_WAIT0()  asm volatile("cp.async.wait_group 0;" ::: "memory")

// ---------------------------------------------------------------------------
// Pre-pass 1: split fp32 row-major -> hi/lo bf16 (same layout)
// ---------------------------------------------------------------------------
__global__ void split_rm(const float* __restrict__ in,
                         __nv_bfloat16* __restrict__ oh,
                         __nv_bfloat16* __restrict__ ol)
{
    size_t i = ((size_t)blockIdx.x * 256 + threadIdx.x) * 4;
    float4 v = *(const float4*)(in + i);
    __nv_bfloat16 h0 = __float2bfloat16(v.x), h1 = __float2bfloat16(v.y);
    __nv_bfloat16 h2 = __float2bfloat16(v.z), h3 = __float2bfloat16(v.w);
    __nv_bfloat162 hp0; hp0.x = h0; hp0.y = h1;
    __nv_bfloat162 hp1; hp1.x = h2; hp1.y = h3;
    *(__nv_bfloat162*)(oh + i)     = hp0;
    *(__nv_bfloat162*)(oh + i + 2) = hp1;
    __nv_bfloat162 lp0, lp1;
    lp0.x = __float2bfloat16(v.x - __bfloat162float(h0));
    lp0.y = __float2bfloat16(v.y - __bfloat162float(h1));
    lp1.x = __float2bfloat16(v.z - __bfloat162float(h2));
    lp1.y = __float2bfloat16(v.w - __bfloat162float(h3));
    *(__nv_bfloat162*)(ol + i)     = lp0;
    *(__nv_bfloat162*)(ol + i + 2) = lp1;
}

// ---------------------------------------------------------------------------
// Pre-pass 2: W [K][N] fp32 -> W^T hi/lo bf16 [N][K]
// ---------------------------------------------------------------------------
__global__ void split_T(const float* __restrict__ W,
                        __nv_bfloat16* __restrict__ oh,
                        __nv_bfloat16* __restrict__ ol, int N)
{
    __shared__ float s[32][33];
    int n0 = blockIdx.x * 32, k0 = blockIdx.y * 32;
    int tx = threadIdx.x, ty = threadIdx.y;
    for (int i = ty; i < 32; i += 8)
        s[i][tx] = W[(size_t)(k0 + i) * N + n0 + tx];
    __syncthreads();
    for (int r = ty; r < 32; r += 8) {
        float v = s[tx][r];                       // = W[k0+tx][n0+r]
        __nv_bfloat16 h = __float2bfloat16(v);
        size_t o = (size_t)(n0 + r) * KDIM + k0 + tx;
        oh[o] = h;
        ol[o] = __float2bfloat16(v - __bfloat162float(h));
    }
}

// ---------------------------------------------------------------------------
// bf16x3 GEMM on mma.sync tensor cores, fp32 accumulate.
// CTA 128(M) x 128(N), BK=32, 8 warps (2M x 4N), warp tile 64x32.
// Smem per stage: Ah/Al/Bh/Bl, each 128 rows x 40 bf16 (80B stride,
// conflict-free for ldmatrix). Double-buffered cp.async pipeline.
// MODE 1: A = x-split, B = Wqkv^T-split, scatter into g_q/g_k/g_v.
// MODE 0: A = attn-out-split, B = Wout^T-split, C row-major + bias.
// ---------------------------------------------------------------------------
#define ROW_B    80            // bytes per smem row (40 bf16)
#define ARR_B    (128 * ROW_B) // 10240
#define OFF_AH   0
#define OFF_AL   ARR_B
#define OFF_BH   (2 * ARR_B)
#define OFF_BL   (3 * ARR_B)
#define STAGE_B  (4 * ARR_B)   // 40960
#define GEMM_SMEM (2 * STAGE_B)// 81920
#define NCHUNK   (KDIM / 32)   // 32

__device__ __forceinline__ void load_chunk(const __nv_bfloat16* __restrict__ Ah,
                                           const __nv_bfloat16* __restrict__ Al,
                                           const __nv_bfloat16* __restrict__ Bh,
                                           const __nv_bfloat16* __restrict__ Bl,
                                           int bm, int bn, int kc,
                                           uint32_t sbase, int tid)
{
#pragma unroll
    for (int i = 0; i < 2; ++i) {
        int idx = tid + i * 256;          // 0..511
        int row = idx >> 2, seg = idx & 3;
        uint32_t so = row * ROW_B + seg * 16;
        size_t ga = (size_t)(bm + row) * KDIM + kc + seg * 8;
        size_t gb = (size_t)(bn + row) * KDIM + kc + seg * 8;
        cp16(sbase + OFF_AH + so, Ah + ga);
        cp16(sbase + OFF_AL + so, Al + ga);
        cp16(sbase + OFF_BH + so, Bh + gb);
        cp16(sbase + OFF_BL + so, Bl + gb);
    }
}

template <int MODE>
__global__ __launch_bounds__(256, 1)
void mma_gemm(const float* __restrict__ bias, float* __restrict__ C, int Ncols)
{
    extern __shared__ char smem[];
    const uint32_t sb0 = smem_to_u32(smem);
    const int tid  = threadIdx.x;
    const int wid  = tid >> 5, lane = tid & 31;
    const int bm = blockIdx.y * 128, bn = blockIdx.x * 128;
    const int warpM = (wid & 1) * 64;
    const int warpN = (wid >> 1) * 32;

    const __nv_bfloat16* Ah = MODE ? g_xh : g_aoh;
    const __nv_bfloat16* Al = MODE ? g_xl : g_aol;
    const __nv_bfloat16* Bh = MODE ? g_wqkvh : g_wouth;
    const __nv_bfloat16* Bl = MODE ? g_wqkvl : g_woutl;

    float acc[4][4][4];
#pragma unroll
    for (int mi = 0; mi < 4; ++mi)
#pragma unroll
        for (int ni = 0; ni < 4; ++ni)
#pragma unroll
            for (int r = 0; r < 4; ++r) acc[mi][ni][r] = 0.f;

    // Prologue: prefetch chunks 0 and 1
    load_chunk(Ah, Al, Bh, Bl, bm, bn, 0, sb0, tid);           CP_COMMIT();
    load_chunk(Ah, Al, Bh, Bl, bm, bn, 32, sb0 + STAGE_B, tid); CP_COMMIT();

    // ldmatrix lane-address components (within a 128-row array)
    const int aRow = lane & 15;              // row within 16-row m-tile
    const int aKo  = (lane >> 4) << 3;       // 0 or 8 (k half)
    const int bRow = ((lane >> 4) << 3) + (lane & 7);  // n within 16 (2 tiles)
    const int bKo  = ((lane >> 3) & 1) << 3; // 0 or 8

    for (int c = 0; c < NCHUNK; ++c) {
        CP_WAIT1();                 // chunk c resident
        __syncthreads();
        const uint32_t st = sb0 + (c & 1) * STAGE_B;

#pragma unroll
        for (int ks = 0; ks < 32; ks += 16) {
            uint32_t afh[4][4], afl[4][4], bfh[4][2], bfl[4][2];
#pragma unroll
            for (int mi = 0; mi < 4; ++mi) {
                uint32_t ao = (warpM + mi * 16 + aRow) * ROW_B + (ks + aKo) * 2;
                ldsm_x4(afh[mi], st + OFF_AH + ao);
                ldsm_x4(afl[mi], st + OFF_AL + ao);
            }
#pragma unroll
            for (int nb = 0; nb < 2; ++nb) {
                uint32_t bo = (warpN + nb * 16 + bRow) * ROW_B + (ks + bKo) * 2;
                uint32_t t[4];
                ldsm_x4(t, st + OFF_BH + bo);
                bfh[nb*2][0] = t[0]; bfh[nb*2][1] = t[1];
                bfh[nb*2+1][0] = t[2]; bfh[nb*2+1][1] = t[3];
                ldsm_x4(t, st + OFF_BL + bo);
                bfl[nb*2][0] = t[0]; bfl[nb*2][1] = t[1];
                bfl[nb*2+1][0] = t[2]; bfl[nb*2+1][1] = t[3];
            }
#pragma unroll
            for (int mi = 0; mi < 4; ++mi)
#pragma unroll
                for (int ni = 0; ni < 4; ++ni) {
                    mma16816(acc[mi][ni], afh[mi], bfh[ni]);
                    mma16816(acc[mi][ni], afh[mi], bfl[ni]);
                    mma16816(acc[mi][ni], afl[mi], bfh[ni]);
                }
        }
        __syncthreads();
        if (c + 2 < NCHUNK) {
            load_chunk(Ah, Al, Bh, Bl, bm, bn, (c + 2) * 32,
                       sb0 + (c & 1) * STAGE_B, tid);
            CP_COMMIT();
        }
    }
    CP_WAIT0();

    // Epilogue. c0,c1 -> (row=lane>>2, col=2*(lane&3)); c2,c3 -> row+8.
    const int qr = lane >> 2;
    const int qc = (lane & 3) * 2;
#pragma unroll
    for (int ni = 0; ni < 4; ++ni) {
        const int n0 = bn + warpN + ni * 8 + qc;
        const float b0 = bias[n0], b1 = bias[n0 + 1];
#pragma unroll
        for (int mi = 0; mi < 4; ++mi) {
            const int m0 = bm + warpM + mi * 16 + qr;
            float2 lo = make_float2(acc[mi][ni][0] + b0, acc[mi][ni][1] + b1);
            float2 hi = make_float2(acc[mi][ni][2] + b0, acc[mi][ni][3] + b1);
            if (MODE == 0) {
                *(float2*)(C + (size_t)m0 * Ncols + n0)       = lo;
                *(float2*)(C + (size_t)(m0 + 8) * Ncols + n0) = hi;
            } else {
                const int which = n0 >> 10;
                const int d     = n0 & 1023;
                const int h     = d >> 6;
                const int dh    = d & 63;
                float* sel = (which == 0 ? g_q : which == 1 ? g_k : g_v);
                {
                    const int bb = m0 >> 11, nn = m0 & 2047;
                    *(float2*)(sel + (((size_t)(bb * NH + h)) * SEQ + nn) * DHEAD + dh) = lo;
                }
                {
                    const int m1 = m0 + 8;
                    const int bb = m1 >> 11, nn = m1 & 2047;
                    *(float2*)(sel + (((size_t)(bb * NH + h)) * SEQ + nn) * DHEAD + dh) = hi;
                }
            }
        }
    }
}

// ---------------------------------------------------------------------------
// Flash attention, fp32 (unchanged math); epilogue writes hi/lo bf16 split.
// ---------------------------------------------------------------------------
#define BQ  128
#define BKV 64
#define ATTN_SMEM ((BQ*64 + 64*64 + 64*64 + BQ*64) * 4)

__global__ __launch_bounds__(256, 2)
void attn_kernel()
{
    extern __shared__ float sm[];
    float* Qs = sm;
    float* Ks = Qs + BQ * 64;
    float* Vs = Ks + 64 * 64;
    float* Ps = Vs + 64 * 64;

    const int tid  = threadIdx.x;
    const int tcol = tid & 15;
    const int trow = tid >> 4;
    const int bh    = blockIdx.y;
    const int qtile = blockIdx.x;

    const float* Q = g_q + (size_t)bh * SEQ * DHEAD + (size_t)qtile * BQ * DHEAD;
    const float* K = g_k + (size_t)bh * SEQ * DHEAD;
    const float* V = g_v + (size_t)bh * SEQ * DHEAD;

    {
        int d0 = tcol * 4;
#pragma unroll
        for (int it = 0; it < 8; ++it) {
            int i = trow + it * 16;
            *(float4*)(Qs + i * 64 + d0) = *(const float4*)(Q + (size_t)i * DHEAD + d0);
        }
    }

    float o[8][4];
    float m2[8], lsum[8];
#pragma unroll
    for (int r = 0; r < 8; ++r) {
        m2[r] = -1e30f; lsum[r] = 0.f;
#pragma unroll
        for (int c = 0; c < 4; ++c) o[r][c] = 0.f;
    }

    const float scale2 = 0.125f * 1.4426950408889634f;
    const int i0 = trow * 8;
    const int j0 = tcol * 4;

    for (int kt = 0; kt < SEQ / BKV; ++kt) {
        __syncthreads();
        {
            int d0 = tcol * 4;
#pragma unroll
            for (int it = 0; it < 4; ++it) {
                int j = trow + it * 16;
                float4 kv = *(const float4*)(K + (size_t)(kt * BKV + j) * DHEAD + d0);
                const float* kp = (const float*)&kv;
#pragma unroll
                for (int c = 0; c < 4; ++c) {
                    int d = d0 + c;
                    int chunk = (j >> 2) ^ ((d >> 2) & 15);
                    Ks[d * 64 + chunk * 4 + (j & 3)] = kp[c];
                }
                *(float4*)(Vs + j * 64 + d0) =
                    *(const float4*)(V + (size_t)(kt * BKV + j) * DHEAD + d0);
            }
        }
        __syncthreads();

        float s[8][4];
#pragma unroll
        for (int r = 0; r < 8; ++r)
#pragma unroll
            for (int c = 0; c < 4; ++c) s[r][c] = 0.f;

#pragma unroll 4
        for (int d = 0; d < 64; d += 4) {
            float bl[4][4];
#pragma unroll
            for (int dd = 0; dd < 4; ++dd) {
                int ddd = d + dd;
                int chunk = tcol ^ ((ddd >> 2) & 15);
                *(float4*)bl[dd] = *(const float4*)(Ks + ddd * 64 + chunk * 4);
            }
#pragma unroll
            for (int r = 0; r < 8; ++r) {
                float4 a4 = *(const float4*)(Qs + (i0 + r) * 64 + d);
#pragma unroll
                for (int c = 0; c < 4; ++c) {
                    s[r][c] = fmaf(a4.x, bl[0][c], s[r][c]);
                    s[r][c] = fmaf(a4.y, bl[1][c], s[r][c]);
                    s[r][c] = fmaf(a4.z, bl[2][c], s[r][c]);
                    s[r][c] = fmaf(a4.w, bl[3][c], s[r][c]);
                }
            }
        }

#pragma unroll
        for (int r = 0; r < 8; ++r) {
            float rmax = -1e30f;
#pragma unroll
            for (int c = 0; c < 4; ++c) {
                s[r][c] *= scale2;
                rmax = fmaxf(rmax, s[r][c]);
            }
#pragma unroll
            for (int off = 8; off >= 1; off >>= 1)
                rmax = fmaxf(rmax, __shfl_xor_sync(0xffffffffu, rmax, off));

            float mnew  = fmaxf(m2[r], rmax);
            float alpha = exp2f(m2[r] - mnew);
            float rs = 0.f;
#pragma unroll
            for (int c = 0; c < 4; ++c) {
                float p = exp2f(s[r][c] - mnew);
                s[r][c] = p;
                rs += p;
            }
#pragma unroll
            for (int off = 8; off >= 1; off >>= 1)
                rs += __shfl_xor_sync(0xffffffffu, rs, off);

            lsum[r] = lsum[r] * alpha + rs;
            m2[r]   = mnew;
#pragma unroll
            for (int c = 0; c < 4; ++c) o[r][c] *= alpha;

            *(float4*)(Ps + (i0 + r) * 64 + j0) =
                make_float4(s[r][0], s[r][1], s[r][2], s[r][3]);
        }
        __syncthreads();

#pragma unroll 4
        for (int j = 0; j < 64; j += 4) {
            float bl[4][4];
#pragma unroll
            for (int jj = 0; jj < 4; ++jj)
                *(float4*)bl[jj] = *(const float4*)(Vs + (j + jj) * 64 + tcol * 4);
#pragma unroll
            for (int r = 0; r < 8; ++r) {
                float4 a4 = *(const float4*)(Ps + (i0 + r) * 64 + j);
#pragma unroll
                for (int c = 0; c < 4; ++c) {
                    o[r][c] = fmaf(a4.x, bl[0][c], o[r][c]);
                    o[r][c] = fmaf(a4.y, bl[1][c], o[r][c]);
                    o[r][c] = fmaf(a4.z, bl[2][c], o[r][c]);
                    o[r][c] = fmaf(a4.w, bl[3][c], o[r][c]);
                }
            }
        }
    }

    // Epilogue: normalize, split to hi/lo bf16 for the out-projection
    const int b = bh >> 4;
    const int h = bh & 15;
#pragma unroll
    for (int r = 0; r < 8; ++r) {
        float inv = __frcp_rn(lsum[r]);
        int n = qtile * BQ + i0 + r;
        size_t off = ((size_t)(b * SEQ + n)) * DMODEL + h * DHEAD + tcol * 4;
        float v[4];
#pragma unroll
        for (int c = 0; c < 4; ++c) v[c] = o[r][c] * inv;
        __nv_bfloat162 hp0, hp1, lp0, lp1;
        hp0.x = __float2bfloat16(v[0]); hp0.y = __float2bfloat16(v[1]);
        hp1.x = __float2bfloat16(v[2]); hp1.y = __float2bfloat16(v[3]);
        lp0.x = __float2bfloat16(v[0] - __bfloat162float(hp0.x));
        lp0.y = __float2bfloat16(v[1] - __bfloat162float(hp0.y));
        lp1.x = __float2bfloat16(v[2] - __bfloat162float(hp1.x));
        lp1.y = __float2bfloat16(v[3] - __bfloat162float(hp1.y));
        *(__nv_bfloat162*)(g_aoh + off)     = hp0;
        *(__nv_bfloat162*)(g_aoh + off + 2) = hp1;
        *(__nv_bfloat162*)(g_aol + off)     = lp0;
        *(__nv_bfloat162*)(g_aol + off + 2) = lp1;
    }
}

// ---------------------------------------------------------------------------
extern "C" void kernel_launch(void* const* d_in, const int* in_sizes, int n_in,
                              void* d_out, int out_size)
{
    const float* x     = (const float*)d_in[0];   // [2,2048,1024]
    const float* Wqkv  = (const float*)d_in[1];   // [1024,3072]
    const float* bqkv  = (const float*)d_in[2];   // [3072]
    const float* Wout  = (const float*)d_in[3];   // [1024,1024]
    const float* bout  = (const float*)d_in[4];   // [1024]
    float* out = (float*)d_out;                   // [2,2048,1024]

    __nv_bfloat16 *xh, *xl, *wqh, *wql, *woh, *wol;
    cudaGetSymbolAddress((void**)&xh,  g_xh);
    cudaGetSymbolAddress((void**)&xl,  g_xl);
    cudaGetSymbolAddress((void**)&wqh, g_wqkvh);
    cudaGetSymbolAddress((void**)&wql, g_wqkvl);
    cudaGetSymbolAddress((void**)&woh, g_wouth);
    cudaGetSymbolAddress((void**)&wol, g_woutl);

    cudaFuncSetAttribute(attn_kernel,
                         cudaFuncAttributeMaxDynamicSharedMemorySize, ATTN_SMEM);
    cudaFuncSetAttribute(mma_gemm<0>,
                         cudaFuncAttributeMaxDynamicSharedMemorySize, GEMM_SMEM);
    cudaFuncSetAttribute(mma_gemm<1>,
                         cudaFuncAttributeMaxDynamicSharedMemorySize, GEMM_SMEM);

    // 0) Splits
    split_rm<<<MROWS * KDIM / 1024, 256>>>(x, xh, xl);
    split_T<<<dim3(3 * DMODEL / 32, KDIM / 32), dim3(32, 8)>>>(Wqkv, wqh, wql, 3 * DMODEL);
    split_T<<<dim3(DMODEL / 32, KDIM / 32), dim3(32, 8)>>>(Wout, woh, wol, DMODEL);

    // 1) QKV projection (mma.sync bf16x3) -> g_q/g_k/g_v
    mma_gemm<1><<<dim3(3 * DMODEL / 128, MROWS / 128), 256, GEMM_SMEM>>>(bqkv, nullptr, 0);

    // 2) Flash attention -> g_aoh/g_aol
    attn_kernel<<<dim3(SEQ / BQ, BATCH * NH), 256, ATTN_SMEM>>>();

    // 3) Output projection (mma.sync bf16x3) -> out
    mma_gemm<0><<<dim3(DMODEL / 128, MROWS / 128), 256, GEMM_SMEM>>>(bout, out, DMODEL);
}

// round 7
// speedup vs baseline: 2.4563x; 1.8208x over previous
#include <cuda_runtime.h>
#include <cuda_bf16.h>
#include <cstdint>

// Problem constants
#define BATCH  2
#define SEQ    2048
#define DMODEL 1024
#define NH     16
#define DHEAD  64
#define MROWS  4096
#define KDIM   1024

// ---------------------------------------------------------------------------
// Device-global scratch (all bf16 hi/lo split pairs)
// ---------------------------------------------------------------------------
__device__ __nv_bfloat16 g_xh[MROWS * KDIM];         // x split (row-major)
__device__ __nv_bfloat16 g_xl[MROWS * KDIM];
__device__ __nv_bfloat16 g_wqkvh[3 * DMODEL * KDIM]; // W_qkv^T: [3072][1024]
__device__ __nv_bfloat16 g_wqkvl[3 * DMODEL * KDIM];
__device__ __nv_bfloat16 g_wouth[DMODEL * KDIM];     // W_out^T: [1024][1024]
__device__ __nv_bfloat16 g_woutl[DMODEL * KDIM];
__device__ __nv_bfloat16 g_qh[BATCH * NH * SEQ * DHEAD];  // [B,H,N,DH]
__device__ __nv_bfloat16 g_ql[BATCH * NH * SEQ * DHEAD];
__device__ __nv_bfloat16 g_kh[BATCH * NH * SEQ * DHEAD];
__device__ __nv_bfloat16 g_kl[BATCH * NH * SEQ * DHEAD];
__device__ __nv_bfloat16 g_vth[BATCH * NH * DHEAD * SEQ]; // V transposed [B,H,DH,N]
__device__ __nv_bfloat16 g_vtl[BATCH * NH * DHEAD * SEQ];
__device__ __nv_bfloat16 g_aoh[MROWS * DMODEL];      // attention out split [M][D]
__device__ __nv_bfloat16 g_aol[MROWS * DMODEL];

// ---------------------------------------------------------------------------
// PTX helpers
// ---------------------------------------------------------------------------
__device__ __forceinline__ uint32_t smem_to_u32(const void* p) {
    uint32_t a;
    asm("{ .reg .u64 t; cvta.to.shared.u64 t, %1; cvt.u32.u64 %0, t; }"
        : "=r"(a) : "l"(p));
    return a;
}
__device__ __forceinline__ void ldsm_x4(uint32_t* r, uint32_t addr) {
    asm volatile("ldmatrix.sync.aligned.m8n8.x4.shared.b16 {%0,%1,%2,%3}, [%4];"
                 : "=r"(r[0]), "=r"(r[1]), "=r"(r[2]), "=r"(r[3]) : "r"(addr));
}
__device__ __forceinline__ void mma16816(float* c, const uint32_t* a, const uint32_t* b) {
    asm volatile("mma.sync.aligned.m16n8k16.row.col.f32.bf16.bf16.f32 "
                 "{%0,%1,%2,%3}, {%4,%5,%6,%7}, {%8,%9}, {%0,%1,%2,%3};"
                 : "+f"(c[0]), "+f"(c[1]), "+f"(c[2]), "+f"(c[3])
                 : "r"(a[0]), "r"(a[1]), "r"(a[2]), "r"(a[3]), "r"(b[0]), "r"(b[1]));
}
__device__ __forceinline__ void cp16(uint32_t dst, const void* src) {
    asm volatile("cp.async.cg.shared.global [%0], [%1], 16;" :: "r"(dst), "l"(src));
}
#define CP_COMMIT() asm volatile("cp.async.commit_group;" ::: "memory")
#define CP_WAIT1()  asm volatile("cp.async.wait_group 1;" ::: "memory")
#define CP_WAIT0()  asm volatile("cp.async.wait_group 0;" ::: "memory")

// pack two floats to bf16x2 (round-to-nearest)
__device__ __forceinline__ uint32_t pack_bf2_rn(float lo, float hi) {
    uint32_t u;
    asm("cvt.rn.bf16x2.f32 %0, %1, %2;" : "=r"(u) : "f"(hi), "f"(lo));
    return u;
}

// ---------------------------------------------------------------------------
// Pre-pass 1: split fp32 row-major -> hi/lo bf16
// ---------------------------------------------------------------------------
__global__ void split_rm(const float* __restrict__ in,
                         __nv_bfloat16* __restrict__ oh,
                         __nv_bfloat16* __restrict__ ol)
{
    size_t i = ((size_t)blockIdx.x * 256 + threadIdx.x) * 4;
    float4 v = *(const float4*)(in + i);
    __nv_bfloat16 h0 = __float2bfloat16(v.x), h1 = __float2bfloat16(v.y);
    __nv_bfloat16 h2 = __float2bfloat16(v.z), h3 = __float2bfloat16(v.w);
    __nv_bfloat162 hp0; hp0.x = h0; hp0.y = h1;
    __nv_bfloat162 hp1; hp1.x = h2; hp1.y = h3;
    *(__nv_bfloat162*)(oh + i)     = hp0;
    *(__nv_bfloat162*)(oh + i + 2) = hp1;
    __nv_bfloat162 lp0, lp1;
    lp0.x = __float2bfloat16(v.x - __bfloat162float(h0));
    lp0.y = __float2bfloat16(v.y - __bfloat162float(h1));
    lp1.x = __float2bfloat16(v.z - __bfloat162float(h2));
    lp1.y = __float2bfloat16(v.w - __bfloat162float(h3));
    *(__nv_bfloat162*)(ol + i)     = lp0;
    *(__nv_bfloat162*)(ol + i + 2) = lp1;
}

// ---------------------------------------------------------------------------
// Pre-pass 2: W [K][N] fp32 -> W^T hi/lo bf16 [N][K]
// ---------------------------------------------------------------------------
__global__ void split_T(const float* __restrict__ W,
                        __nv_bfloat16* __restrict__ oh,
                        __nv_bfloat16* __restrict__ ol, int N)
{
    __shared__ float s[32][33];
    int n0 = blockIdx.x * 32, k0 = blockIdx.y * 32;
    int tx = threadIdx.x, ty = threadIdx.y;
    for (int i = ty; i < 32; i += 8)
        s[i][tx] = W[(size_t)(k0 + i) * N + n0 + tx];
    __syncthreads();
    for (int r = ty; r < 32; r += 8) {
        float v = s[tx][r];
        __nv_bfloat16 h = __float2bfloat16(v);
        size_t o = (size_t)(n0 + r) * KDIM + k0 + tx;
        oh[o] = h;
        ol[o] = __float2bfloat16(v - __bfloat162float(h));
    }
}

// ---------------------------------------------------------------------------
// bf16x3 GEMM on mma.sync. CTA 128x128, BK=32, 8 warps (2M x 4N).
// MODE 1: A = x-split, B = Wqkv^T-split; epilogue -> q/k hi/lo + v^T hi/lo.
// MODE 0: A = attn-out-split, B = Wout^T-split; C row-major fp32 + bias.
// ---------------------------------------------------------------------------
#define ROW_B    80
#define ARR_B    (128 * ROW_B)
#define OFF_AH   0
#define OFF_AL   ARR_B
#define OFF_BH   (2 * ARR_B)
#define OFF_BL   (3 * ARR_B)
#define STAGE_B  (4 * ARR_B)
#define GEMM_SMEM (2 * STAGE_B)
#define NCHUNK   (KDIM / 32)

__device__ __forceinline__ void load_chunk(const __nv_bfloat16* __restrict__ Ah,
                                           const __nv_bfloat16* __restrict__ Al,
                                           const __nv_bfloat16* __restrict__ Bh,
                                           const __nv_bfloat16* __restrict__ Bl,
                                           int bm, int bn, int kc,
                                           uint32_t sbase, int tid)
{
#pragma unroll
    for (int i = 0; i < 2; ++i) {
        int idx = tid + i * 256;
        int row = idx >> 2, seg = idx & 3;
        uint32_t so = row * ROW_B + seg * 16;
        size_t ga = (size_t)(bm + row) * KDIM + kc + seg * 8;
        size_t gb = (size_t)(bn + row) * KDIM + kc + seg * 8;
        cp16(sbase + OFF_AH + so, Ah + ga);
        cp16(sbase + OFF_AL + so, Al + ga);
        cp16(sbase + OFF_BH + so, Bh + gb);
        cp16(sbase + OFF_BL + so, Bl + gb);
    }
}

template <int MODE>
__global__ __launch_bounds__(256, 1)
void mma_gemm(const float* __restrict__ bias, float* __restrict__ C, int Ncols)
{
    extern __shared__ char smem[];
    const uint32_t sb0 = smem_to_u32(smem);
    const int tid  = threadIdx.x;
    const int wid  = tid >> 5, lane = tid & 31;
    const int bm = blockIdx.y * 128, bn = blockIdx.x * 128;
    const int warpM = (wid & 1) * 64;
    const int warpN = (wid >> 1) * 32;

    const __nv_bfloat16* Ah = MODE ? g_xh : g_aoh;
    const __nv_bfloat16* Al = MODE ? g_xl : g_aol;
    const __nv_bfloat16* Bh = MODE ? g_wqkvh : g_wouth;
    const __nv_bfloat16* Bl = MODE ? g_wqkvl : g_woutl;

    float acc[4][4][4];
#pragma unroll
    for (int mi = 0; mi < 4; ++mi)
#pragma unroll
        for (int ni = 0; ni < 4; ++ni)
#pragma unroll
            for (int r = 0; r < 4; ++r) acc[mi][ni][r] = 0.f;

    load_chunk(Ah, Al, Bh, Bl, bm, bn, 0, sb0, tid);           CP_COMMIT();
    load_chunk(Ah, Al, Bh, Bl, bm, bn, 32, sb0 + STAGE_B, tid); CP_COMMIT();

    const int aRow = lane & 15;
    const int aKo  = (lane >> 4) << 3;
    const int bRow = ((lane >> 4) << 3) + (lane & 7);
    const int bKo  = ((lane >> 3) & 1) << 3;

    for (int c = 0; c < NCHUNK; ++c) {
        CP_WAIT1();
        __syncthreads();
        const uint32_t st = sb0 + (c & 1) * STAGE_B;

#pragma unroll
        for (int ks = 0; ks < 32; ks += 16) {
            uint32_t afh[4][4], afl[4][4], bfh[4][2], bfl[4][2];
#pragma unroll
            for (int mi = 0; mi < 4; ++mi) {
                uint32_t ao = (warpM + mi * 16 + aRow) * ROW_B + (ks + aKo) * 2;
                ldsm_x4(afh[mi], st + OFF_AH + ao);
                ldsm_x4(afl[mi], st + OFF_AL + ao);
            }
#pragma unroll
            for (int nb = 0; nb < 2; ++nb) {
                uint32_t bo = (warpN + nb * 16 + bRow) * ROW_B + (ks + bKo) * 2;
                uint32_t t[4];
                ldsm_x4(t, st + OFF_BH + bo);
                bfh[nb*2][0] = t[0]; bfh[nb*2][1] = t[1];
                bfh[nb*2+1][0] = t[2]; bfh[nb*2+1][1] = t[3];
                ldsm_x4(t, st + OFF_BL + bo);
                bfl[nb*2][0] = t[0]; bfl[nb*2][1] = t[1];
                bfl[nb*2+1][0] = t[2]; bfl[nb*2+1][1] = t[3];
            }
#pragma unroll
            for (int mi = 0; mi < 4; ++mi)
#pragma unroll
                for (int ni = 0; ni < 4; ++ni) {
                    mma16816(acc[mi][ni], afh[mi], bfh[ni]);
                    mma16816(acc[mi][ni], afh[mi], bfl[ni]);
                    mma16816(acc[mi][ni], afl[mi], bfh[ni]);
                }
        }
        __syncthreads();
        if (c + 2 < NCHUNK) {
            load_chunk(Ah, Al, Bh, Bl, bm, bn, (c + 2) * 32,
                       sb0 + (c & 1) * STAGE_B, tid);
            CP_COMMIT();
        }
    }
    CP_WAIT0();

    const int qr = lane >> 2;
    const int qc = (lane & 3) * 2;
#pragma unroll
    for (int ni = 0; ni < 4; ++ni) {
        const int n0 = bn + warpN + ni * 8 + qc;
        const float b0 = bias[n0], b1 = bias[n0 + 1];
#pragma unroll
        for (int mi = 0; mi < 4; ++mi) {
            const int m0 = bm + warpM + mi * 16 + qr;
            float v0 = acc[mi][ni][0] + b0, v1 = acc[mi][ni][1] + b1;   // row m0
            float v2 = acc[mi][ni][2] + b0, v3 = acc[mi][ni][3] + b1;   // row m0+8
            if (MODE == 0) {
                *(float2*)(C + (size_t)m0 * Ncols + n0)       = make_float2(v0, v1);
                *(float2*)(C + (size_t)(m0 + 8) * Ncols + n0) = make_float2(v2, v3);
            } else {
                const int which = n0 >> 10;
                const int d     = n0 & 1023;
                const int h     = d >> 6;
                const int dh    = d & 63;
                __nv_bfloat16 h0 = __float2bfloat16(v0), h1 = __float2bfloat16(v1);
                __nv_bfloat16 h2 = __float2bfloat16(v2), h3 = __float2bfloat16(v3);
                __nv_bfloat16 l0 = __float2bfloat16(v0 - __bfloat162float(h0));
                __nv_bfloat16 l1 = __float2bfloat16(v1 - __bfloat162float(h1));
                __nv_bfloat16 l2 = __float2bfloat16(v2 - __bfloat162float(h2));
                __nv_bfloat16 l3 = __float2bfloat16(v3 - __bfloat162float(h3));
                const int bb0 = m0 >> 11, nn0 = m0 & 2047;
                const int m1 = m0 + 8;
                const int bb1 = m1 >> 11, nn1 = m1 & 2047;
                if (which < 2) {
                    __nv_bfloat16* ah = which ? g_kh : g_qh;
                    __nv_bfloat16* al = which ? g_kl : g_ql;
                    size_t i0 = (((size_t)(bb0 * NH + h)) * SEQ + nn0) * DHEAD + dh;
                    size_t i1 = (((size_t)(bb1 * NH + h)) * SEQ + nn1) * DHEAD + dh;
                    __nv_bfloat162 p;
                    p.x = h0; p.y = h1; *(__nv_bfloat162*)(ah + i0) = p;
                    p.x = l0; p.y = l1; *(__nv_bfloat162*)(al + i0) = p;
                    p.x = h2; p.y = h3; *(__nv_bfloat162*)(ah + i1) = p;
                    p.x = l2; p.y = l3; *(__nv_bfloat162*)(al + i1) = p;
                } else {
                    // V transposed: [B,H,DH,N]
                    size_t base0 = ((size_t)(bb0 * NH + h)) * DHEAD * SEQ;
                    size_t base1 = ((size_t)(bb1 * NH + h)) * DHEAD * SEQ;
                    g_vth[base0 + (size_t)dh * SEQ + nn0]       = h0;
                    g_vth[base0 + (size_t)(dh + 1) * SEQ + nn0] = h1;
                    g_vtl[base0 + (size_t)dh * SEQ + nn0]       = l0;
                    g_vtl[base0 + (size_t)(dh + 1) * SEQ + nn0] = l1;
                    g_vth[base1 + (size_t)dh * SEQ + nn1]       = h2;
                    g_vth[base1 + (size_t)(dh + 1) * SEQ + nn1] = h3;
                    g_vtl[base1 + (size_t)dh * SEQ + nn1]       = l2;
                    g_vtl[base1 + (size_t)(dh + 1) * SEQ + nn1] = l3;
                }
            }
        }
    }
}

// ---------------------------------------------------------------------------
// Tensor-core flash attention, bf16x3 split. CTA = 128 queries x one (b,h).
// 8 warps, each owns 16 query rows. BKV=64, double-buffered K/V stages.
// Smem rows padded to 72 halves (144B stride -> ldmatrix conflict-free).
// ---------------------------------------------------------------------------
#define AROW_B   144
#define OFF_QH   0
#define OFF_QL   18432
#define OFF_KST  36864        /* + buf*18432; Kl at +9216 */
#define OFF_VST  73728        /* + buf*18432; Vtl at +9216 */
#define ATTN_SMEM 110592
#define NKT      (SEQ / 64)   /* 32 */

__device__ __forceinline__ void attn_load_kv(uint32_t sb, int bh, int kt, int buf, int tid)
{
    const __nv_bfloat16* kh = g_kh + (size_t)bh * SEQ * DHEAD;
    const __nv_bfloat16* kl = g_kl + (size_t)bh * SEQ * DHEAD;
    const __nv_bfloat16* vh = g_vth + (size_t)bh * DHEAD * SEQ;
    const __nv_bfloat16* vl = g_vtl + (size_t)bh * DHEAD * SEQ;
#pragma unroll
    for (int i = 0; i < 8; ++i) {
        int idx = tid + i * 256;           // 0..2047
        int arr = idx >> 9;                // 0:Kh 1:Kl 2:Vth 3:Vtl
        int a   = idx & 511;
        int row = a >> 3, seg = a & 7;
        uint32_t dst = sb + (arr < 2 ? OFF_KST : OFF_VST) + buf * 18432
                     + (arr & 1) * 9216 + row * AROW_B + seg * 16;
        const __nv_bfloat16* src;
        if (arr == 0)      src = kh + (size_t)(kt * 64 + row) * DHEAD + seg * 8;
        else if (arr == 1) src = kl + (size_t)(kt * 64 + row) * DHEAD + seg * 8;
        else if (arr == 2) src = vh + (size_t)row * SEQ + kt * 64 + seg * 8;
        else               src = vl + (size_t)row * SEQ + kt * 64 + seg * 8;
        cp16(dst, src);
    }
}

__global__ __launch_bounds__(256, 1)
void attn_mma()
{
    extern __shared__ char smem[];
    const uint32_t sb = smem_to_u32(smem);
    const int tid = threadIdx.x;
    const int wid = tid >> 5, lane = tid & 31;
    const int bh = blockIdx.y, qtile = blockIdx.x;

    const int aRow = lane & 15;
    const int aKo  = (lane >> 4) << 3;
    const int bRow = ((lane >> 4) << 3) + (lane & 7);
    const int bKo  = ((lane >> 3) & 1) << 3;

    // Prologue: Q tiles (hi/lo) + first K/V stage
    {
        const __nv_bfloat16* qh = g_qh + ((size_t)bh * SEQ + qtile * 128) * DHEAD;
        const __nv_bfloat16* ql = g_ql + ((size_t)bh * SEQ + qtile * 128) * DHEAD;
#pragma unroll
        for (int i = 0; i < 8; ++i) {
            int idx = tid + i * 256;        // 0..2047
            int arr = idx >> 10;            // 0:Qh 1:Ql
            int a   = idx & 1023;
            int row = a >> 3, seg = a & 7;
            uint32_t dst = sb + (arr ? OFF_QL : OFF_QH) + row * AROW_B + seg * 16;
            const __nv_bfloat16* src = (arr ? ql : qh) + (size_t)row * DHEAD + seg * 8;
            cp16(dst, src);
        }
        CP_COMMIT();
        attn_load_kv(sb, bh, 0, 0, tid);
        CP_COMMIT();
    }

    float o[8][4];
#pragma unroll
    for (int ni = 0; ni < 8; ++ni)
#pragma unroll
        for (int r = 0; r < 4; ++r) o[ni][r] = 0.f;
    float mA = -1e30f, mB = -1e30f, lA = 0.f, lB = 0.f;
    const float scale2 = 0.125f * 1.4426950408889634f;  // 1/sqrt(64)*log2(e)

    for (int kt = 0; kt < NKT; ++kt) {
        CP_WAIT0();
        __syncthreads();
        const int buf = kt & 1;
        const uint32_t kbase = sb + OFF_KST + buf * 18432;
        const uint32_t vbase = sb + OFF_VST + buf * 18432;

        // ---- S = Q K^T (3-pass split) ----
        float c[8][4];
#pragma unroll
        for (int ni = 0; ni < 8; ++ni)
#pragma unroll
            for (int r = 0; r < 4; ++r) c[ni][r] = 0.f;

#pragma unroll
        for (int ki = 0; ki < 4; ++ki) {
            uint32_t ah[4], al[4];
            uint32_t qo = (wid * 16 + aRow) * AROW_B + (ki * 16 + aKo) * 2;
            ldsm_x4(ah, sb + OFF_QH + qo);
            ldsm_x4(al, sb + OFF_QL + qo);
#pragma unroll
            for (int nb = 0; nb < 4; ++nb) {
                uint32_t ko = (nb * 16 + bRow) * AROW_B + (ki * 16 + bKo) * 2;
                uint32_t th[4], tl[4];
                ldsm_x4(th, kbase + ko);
                ldsm_x4(tl, kbase + 9216 + ko);
                mma16816(c[nb*2],   ah, th);     mma16816(c[nb*2],   ah, tl);
                mma16816(c[nb*2],   al, th);
                mma16816(c[nb*2+1], ah, th + 2); mma16816(c[nb*2+1], ah, tl + 2);
                mma16816(c[nb*2+1], al, th + 2);
            }
        }

        // ---- prefetch next K/V stage (overlaps softmax + PV) ----
        if (kt + 1 < NKT) {
            attn_load_kv(sb, bh, kt + 1, buf ^ 1, tid);
            CP_COMMIT();
        }

        // ---- online softmax on fragments (rows rA=lane>>2, rB=rA+8) ----
        {
            float mxA = -1e30f, mxB = -1e30f;
#pragma unroll
            for (int ni = 0; ni < 8; ++ni) {
                mxA = fmaxf(mxA, fmaxf(c[ni][0], c[ni][1]));
                mxB = fmaxf(mxB, fmaxf(c[ni][2], c[ni][3]));
            }
            mxA = fmaxf(mxA, __shfl_xor_sync(0xffffffffu, mxA, 1));
            mxA = fmaxf(mxA, __shfl_xor_sync(0xffffffffu, mxA, 2));
            mxB = fmaxf(mxB, __shfl_xor_sync(0xffffffffu, mxB, 1));
            mxB = fmaxf(mxB, __shfl_xor_sync(0xffffffffu, mxB, 2));

            float mnA = fmaxf(mA, mxA * scale2);
            float mnB = fmaxf(mB, mxB * scale2);
            float alphaA = exp2f(mA - mnA);
            float alphaB = exp2f(mB - mnB);
            mA = mnA; mB = mnB;

            float rsA = 0.f, rsB = 0.f;
#pragma unroll
            for (int ni = 0; ni < 8; ++ni) {
                c[ni][0] = exp2f(fmaf(c[ni][0], scale2, -mnA)); rsA += c[ni][0];
                c[ni][1] = exp2f(fmaf(c[ni][1], scale2, -mnA)); rsA += c[ni][1];
                c[ni][2] = exp2f(fmaf(c[ni][2], scale2, -mnB)); rsB += c[ni][2];
                c[ni][3] = exp2f(fmaf(c[ni][3], scale2, -mnB)); rsB += c[ni][3];
            }
            rsA += __shfl_xor_sync(0xffffffffu, rsA, 1);
            rsA += __shfl_xor_sync(0xffffffffu, rsA, 2);
            rsB += __shfl_xor_sync(0xffffffffu, rsB, 1);
            rsB += __shfl_xor_sync(0xffffffffu, rsB, 2);
            lA = lA * alphaA + rsA;
            lB = lB * alphaB + rsB;
#pragma unroll
            for (int ni = 0; ni < 8; ++ni) {
                o[ni][0] *= alphaA; o[ni][1] *= alphaA;
                o[ni][2] *= alphaB; o[ni][3] *= alphaB;
            }
        }

        // ---- O += P V (3-pass split; P from registers, no smem) ----
#pragma unroll
        for (int ki = 0; ki < 4; ++ki) {
            uint32_t pah[4], pal[4];
#pragma unroll
            for (int half = 0; half < 2; ++half) {
                const float* pc = c[2 * ki + half];
                uint32_t u0 = __float_as_uint(pc[0]), u1 = __float_as_uint(pc[1]);
                uint32_t u2 = __float_as_uint(pc[2]), u3 = __float_as_uint(pc[3]);
                pah[half * 2]     = __byte_perm(u0, u1, 0x7632);
                pah[half * 2 + 1] = __byte_perm(u2, u3, 0x7632);
                float h0 = __uint_as_float(u0 & 0xFFFF0000u);
                float h1 = __uint_as_float(u1 & 0xFFFF0000u);
                float h2 = __uint_as_float(u2 & 0xFFFF0000u);
                float h3 = __uint_as_float(u3 & 0xFFFF0000u);
                pal[half * 2]     = pack_bf2_rn(pc[0] - h0, pc[1] - h1);
                pal[half * 2 + 1] = pack_bf2_rn(pc[2] - h2, pc[3] - h3);
            }
            uint32_t aH[4] = { pah[0], pah[1], pah[2], pah[3] };
            uint32_t aL[4] = { pal[0], pal[1], pal[2], pal[3] };
#pragma unroll
            for (int db = 0; db < 4; ++db) {
                uint32_t vo = (db * 16 + bRow) * AROW_B + (ki * 16 + bKo) * 2;
                uint32_t th[4], tl[4];
                ldsm_x4(th, vbase + vo);
                ldsm_x4(tl, vbase + 9216 + vo);
                mma16816(o[db*2],   aH, th);     mma16816(o[db*2],   aH, tl);
                mma16816(o[db*2],   aL, th);
                mma16816(o[db*2+1], aH, th + 2); mma16816(o[db*2+1], aH, tl + 2);
                mma16816(o[db*2+1], aL, th + 2);
            }
        }
    }

    // ---- epilogue: normalize, split, write g_aoh/g_aol ----
    const int b = bh >> 4;
    const int h = bh & 15;
    const float invA = __frcp_rn(lA), invB = __frcp_rn(lB);
    const int rA = qtile * 128 + wid * 16 + (lane >> 2);
    const int rB = rA + 8;
    const int qc = (lane & 3) * 2;
#pragma unroll
    for (int ni = 0; ni < 8; ++ni) {
        const int col = h * 64 + ni * 8 + qc;
        float v0 = o[ni][0] * invA, v1 = o[ni][1] * invA;
        float v2 = o[ni][2] * invB, v3 = o[ni][3] * invB;
        __nv_bfloat16 h0 = __float2bfloat16(v0), h1 = __float2bfloat16(v1);
        __nv_bfloat16 h2 = __float2bfloat16(v2), h3 = __float2bfloat16(v3);
        __nv_bfloat162 p;
        size_t iA = ((size_t)(b * SEQ + rA)) * DMODEL + col;
        size_t iB = ((size_t)(b * SEQ + rB)) * DMODEL + col;
        p.x = h0; p.y = h1; *(__nv_bfloat162*)(g_aoh + iA) = p;
        p.x = h2; p.y = h3; *(__nv_bfloat162*)(g_aoh + iB) = p;
        p.x = __float2bfloat16(v0 - __bfloat162float(h0));
        p.y = __float2bfloat16(v1 - __bfloat162float(h1));
        *(__nv_bfloat162*)(g_aol + iA) = p;
        p.x = __float2bfloat16(v2 - __bfloat162float(h2));
        p.y = __float2bfloat16(v3 - __bfloat162float(h3));
        *(__nv_bfloat162*)(g_aol + iB) = p;
    }
}

// ---------------------------------------------------------------------------
extern "C" void kernel_launch(void* const* d_in, const int* in_sizes, int n_in,
                              void* d_out, int out_size)
{
    const float* x     = (const float*)d_in[0];
    const float* Wqkv  = (const float*)d_in[1];
    const float* bqkv  = (const float*)d_in[2];
    const float* Wout  = (const float*)d_in[3];
    const float* bout  = (const float*)d_in[4];
    float* out = (float*)d_out;

    __nv_bfloat16 *xh, *xl, *wqh, *wql, *woh, *wol;
    cudaGetSymbolAddress((void**)&xh,  g_xh);
    cudaGetSymbolAddress((void**)&xl,  g_xl);
    cudaGetSymbolAddress((void**)&wqh, g_wqkvh);
    cudaGetSymbolAddress((void**)&wql, g_wqkvl);
    cudaGetSymbolAddress((void**)&woh, g_wouth);
    cudaGetSymbolAddress((void**)&wol, g_woutl);

    cudaFuncSetAttribute(attn_mma,
                         cudaFuncAttributeMaxDynamicSharedMemorySize, ATTN_SMEM);
    cudaFuncSetAttribute(mma_gemm<0>,
                         cudaFuncAttributeMaxDynamicSharedMemorySize, GEMM_SMEM);
    cudaFuncSetAttribute(mma_gemm<1>,
                         cudaFuncAttributeMaxDynamicSharedMemorySize, GEMM_SMEM);

    // 0) Splits
    split_rm<<<MROWS * KDIM / 1024, 256>>>(x, xh, xl);
    split_T<<<dim3(3 * DMODEL / 32, KDIM / 32), dim3(32, 8)>>>(Wqkv, wqh, wql, 3 * DMODEL);
    split_T<<<dim3(DMODEL / 32, KDIM / 32), dim3(32, 8)>>>(Wout, woh, wol, DMODEL);

    // 1) QKV projection -> q/k hi/lo + v^T hi/lo
    mma_gemm<1><<<dim3(3 * DMODEL / 128, MROWS / 128), 256, GEMM_SMEM>>>(bqkv, nullptr, 0);

    // 2) Tensor-core flash attention -> g_aoh/g_aol
    attn_mma<<<dim3(SEQ / 128, BATCH * NH), 256, ATTN_SMEM>>>();

    // 3) Output projection -> out
    mma_gemm<0><<<dim3(DMODEL / 128, MROWS / 128), 256, GEMM_SMEM>>>(bout, out, DMODEL);
}